// round 2
// baseline (speedup 1.0000x reference)
#include <cuda_runtime.h>

// SecureSwishFeedForward: out = swish_poly(X @ W1^T + b1) @ W2^T + b2
// X: [M=8192, D=1024] fp32, W1: [F=4096, D], W2: [D, F], all row-major.
// Both GEMMs are A[M,K] @ B[N,K]^T with K contiguous in both operands.
//
// Round 1 baseline: classic fp32 tiled SGEMM (BM=BN=128, BK=16, 8x8 per
// thread, 256 threads), bias+activation fused into the epilogue.
// Intermediate H [M,F] lives in a __device__ global scratch (no allocs).

#define BM 128
#define BN 128
#define BK 16
#define TM 8
#define TN 8
#define NTHREADS 256

// 8192 * 4096 floats = 128 MB scratch for the hidden activation.
__device__ float g_mid[8192UL * 4096UL];

template<bool SWISH>
__global__ __launch_bounds__(NTHREADS, 2)
void gemm_bias_act(const float* __restrict__ A,   // [M, K]
                   const float* __restrict__ B,   // [N, K]
                   const float* __restrict__ bias,// [N]
                   float* __restrict__ C,         // [M, N]
                   int M, int N, int K)
{
    __shared__ __align__(16) float As[BK][BM + 4];
    __shared__ __align__(16) float Bs[BK][BN + 4];

    const int tid = threadIdx.x;
    const int tx  = tid & 15;   // 16 thread-cols
    const int ty  = tid >> 4;   // 16 thread-rows

    const int rowBase = blockIdx.y * BM;
    const int colBase = blockIdx.x * BN;

    const float* Ab = A + (size_t)rowBase * K;
    const float* Bb = B + (size_t)colBase * K;

    float acc[TM][TN];
#pragma unroll
    for (int i = 0; i < TM; i++)
#pragma unroll
        for (int j = 0; j < TN; j++) acc[i][j] = 0.0f;

    for (int k0 = 0; k0 < K; k0 += BK) {
        // Cooperative load: 128 rows x 16 k = 512 float4 per operand,
        // 256 threads -> 2 float4 each, stored k-major (transposed) in smem.
#pragma unroll
        for (int it = 0; it < 2; it++) {
            const int t  = tid + it * NTHREADS;
            const int r  = t >> 2;            // 0..127 tile row
            const int k4 = (t & 3) * 4;       // 0,4,8,12
            float4 va = *reinterpret_cast<const float4*>(Ab + (size_t)r * K + k0 + k4);
            As[k4 + 0][r] = va.x; As[k4 + 1][r] = va.y;
            As[k4 + 2][r] = va.z; As[k4 + 3][r] = va.w;
            float4 vb = *reinterpret_cast<const float4*>(Bb + (size_t)r * K + k0 + k4);
            Bs[k4 + 0][r] = vb.x; Bs[k4 + 1][r] = vb.y;
            Bs[k4 + 2][r] = vb.z; Bs[k4 + 3][r] = vb.w;
        }
        __syncthreads();

#pragma unroll
        for (int k = 0; k < BK; k++) {
            float af[TM], bf[TN];
            float4 a0 = *reinterpret_cast<const float4*>(&As[k][ty * TM]);
            float4 a1 = *reinterpret_cast<const float4*>(&As[k][ty * TM + 4]);
            af[0] = a0.x; af[1] = a0.y; af[2] = a0.z; af[3] = a0.w;
            af[4] = a1.x; af[5] = a1.y; af[6] = a1.z; af[7] = a1.w;
            float4 b0 = *reinterpret_cast<const float4*>(&Bs[k][tx * TN]);
            float4 b1v = *reinterpret_cast<const float4*>(&Bs[k][tx * TN + 4]);
            bf[0] = b0.x; bf[1] = b0.y; bf[2] = b0.z; bf[3] = b0.w;
            bf[4] = b1v.x; bf[5] = b1v.y; bf[6] = b1v.z; bf[7] = b1v.w;
#pragma unroll
            for (int i = 0; i < TM; i++)
#pragma unroll
                for (int j = 0; j < TN; j++)
                    acc[i][j] = fmaf(af[i], bf[j], acc[i][j]);
        }
        __syncthreads();
    }

    // Epilogue: bias (+ optional poly-swish), vectorized float4 stores.
    const int colT = colBase + tx * TN;
    float4 biasv0 = *reinterpret_cast<const float4*>(bias + colT);
    float4 biasv1 = *reinterpret_cast<const float4*>(bias + colT + 4);
    const float bv[TN] = {biasv0.x, biasv0.y, biasv0.z, biasv0.w,
                          biasv1.x, biasv1.y, biasv1.z, biasv1.w};
#pragma unroll
    for (int i = 0; i < TM; i++) {
        const int row = rowBase + ty * TM + i;
        float v[TN];
#pragma unroll
        for (int j = 0; j < TN; j++) {
            float h = acc[i][j] + bv[j];
            if (SWISH) {
                // h * (0.5 + 0.25h - 0.0208h^3)
                float h2 = h * h;
                float sig = fmaf(-0.0208f * h2, h, fmaf(0.25f, h, 0.5f));
                v[j] = h * sig;
            } else {
                v[j] = h;
            }
        }
        float4* out0 = reinterpret_cast<float4*>(C + (size_t)row * N + colT);
        out0[0] = make_float4(v[0], v[1], v[2], v[3]);
        out0[1] = make_float4(v[4], v[5], v[6], v[7]);
    }
}

extern "C" void kernel_launch(void* const* d_in, const int* in_sizes, int n_in,
                              void* d_out, int out_size)
{
    const float* X  = (const float*)d_in[0]; // [M, D]
    const float* W1 = (const float*)d_in[1]; // [F, D]
    const float* b1 = (const float*)d_in[2]; // [F]
    const float* W2 = (const float*)d_in[3]; // [D, F]
    const float* b2 = (const float*)d_in[4]; // [D]
    float* out = (float*)d_out;              // [M, D]

    const int F = in_sizes[2];               // 4096
    const int D = in_sizes[4];               // 1024
    const int M = in_sizes[0] / D;           // 8192

    float* mid = nullptr;
    cudaGetSymbolAddress((void**)&mid, g_mid);

    // GEMM1: H = swish(X @ W1^T + b1)   [M, F], K = D
    {
        dim3 grid(F / BN, M / BM);
        gemm_bias_act<true><<<grid, NTHREADS>>>(X, W1, b1, mid, M, F, D);
    }
    // GEMM2: out = H @ W2^T + b2        [M, D], K = F
    {
        dim3 grid(D / BN, M / BM);
        gemm_bias_act<false><<<grid, NTHREADS>>>(mid, W2, b2, out, M, D, F);
    }
}

// round 6
// speedup vs baseline: 3.3535x; 3.3535x over previous
#include <cuda_runtime.h>
#include <cstdint>

// SecureSwishFeedForward via legacy TF32 mma.sync (m16n8k8) — the harness's
// PTX stage targets compute_103 (no 'a'), so tcgen05 is unavailable; HMMA.TF32
// is the fastest tensor path that compiles.
//
// out = swish_poly(X @ W1^T + b1) @ W2^T + b2
// X:[8192,1024] W1:[4096,1024] W2:[1024,4096], fp32 row-major, K contiguous.
//
// GEMM: 128x128x32 CTA tile, 8 warps (64x32 warp tile = 4x4 m16n8k8 frags),
// 3-stage cp.async pipeline, padded smem (stride 36 floats, conflict-free
// fragment loads), fused bias + poly-swish epilogue.
// Inputs pre-rounded to tf32 (RN); GEMM1 output re-rounded likewise.

#define BM 128
#define BN 128
#define BK 32
#define PAD 4
#define LDSS (BK + PAD)                      // 36 floats
#define A_STAGE_F (BM * LDSS)                // floats per A stage (4608)
#define STAGE_F   (2 * A_STAGE_F)            // floats per stage (9216)
#define STAGES 3
#define NTHREADS 256
#define SMEM_DYN (STAGES * STAGE_F * 4)      // 110592 bytes

__device__ float g_mid[8192UL * 4096UL];
__device__ float g_Xr [8192UL * 1024UL];
__device__ float g_W1r[4096UL * 1024UL];
__device__ float g_W2r[1024UL * 4096UL];

__device__ __forceinline__ void cpa16(const float* smem_dst, const float* gsrc) {
    uint32_t a;
    asm("{ .reg .u64 t; cvta.to.shared.u64 t, %1; cvt.u32.u64 %0, t; }"
        : "=r"(a) : "l"(smem_dst));
    asm volatile("cp.async.cg.shared.global [%0], [%1], 16;" :: "r"(a), "l"(gsrc));
}

template<bool SWISH, bool ROUND_OUT>
__global__ __launch_bounds__(NTHREADS, 2)
void ffn_gemm(const float* __restrict__ A,    // [M, K] tf32-rounded
              const float* __restrict__ B,    // [N, K] tf32-rounded
              const float* __restrict__ bias, // [N]
              float* __restrict__ C,          // [M, N]
              int M, int N, int K)
{
    extern __shared__ __align__(16) float smem[];

    const int tid  = threadIdx.x;
    const int wid  = tid >> 5, lane = tid & 31;
    const int wr   = wid >> 2, wc   = wid & 3;   // 2x4 warp grid
    const int lr   = lane >> 2, lc  = lane & 3;
    const int rowBase = blockIdx.y * BM;
    const int colBase = blockIdx.x * BN;
    const int NC = K / BK;

    float acc[4][4][4];
#pragma unroll
    for (int mi = 0; mi < 4; mi++)
#pragma unroll
        for (int ni = 0; ni < 4; ni++)
#pragma unroll
            for (int e = 0; e < 4; e++) acc[mi][ni][e] = 0.0f;

    // Stage load: A tile 128 rows x 8 float4, B tile same; 8 cp.async/thread.
    const int ldrow = tid >> 3;        // 0..31 base row (x4 iters -> 128)
    const int ldq   = (tid & 7) * 4;   // float offset within row
    #define LOAD_STAGE(s, c) do {                                              \
        float* sa_ = smem + (s) * STAGE_F;                                     \
        float* sb_ = sa_ + A_STAGE_F;                                          \
        _Pragma("unroll")                                                      \
        for (int it_ = 0; it_ < 4; it_++) {                                    \
            int row_ = ldrow + it_ * 32;                                       \
            cpa16(sa_ + row_ * LDSS + ldq,                                     \
                  A + (size_t)(rowBase + row_) * K + (c) * BK + ldq);          \
        }                                                                      \
        _Pragma("unroll")                                                      \
        for (int it_ = 0; it_ < 4; it_++) {                                    \
            int row_ = ldrow + it_ * 32;                                       \
            cpa16(sb_ + row_ * LDSS + ldq,                                     \
                  B + (size_t)(colBase + row_) * K + (c) * BK + ldq);          \
        }                                                                      \
    } while (0)

    // Prologue: fill STAGES-1 stages.
#pragma unroll
    for (int s = 0; s < STAGES - 1; s++) {
        if (s < NC) LOAD_STAGE(s, s);
        asm volatile("cp.async.commit_group;" ::: "memory");
    }

    for (int c = 0; c < NC; c++) {
        if (c + STAGES - 1 < NC) {
            int s = (c + STAGES - 1) % STAGES;
            LOAD_STAGE(s, c + STAGES - 1);
        }
        asm volatile("cp.async.commit_group;" ::: "memory");
        asm volatile("cp.async.wait_group %0;" :: "n"(STAGES - 1) : "memory");
        __syncthreads();

        const float* sa = smem + (c % STAGES) * STAGE_F;
        const float* sb = sa + A_STAGE_F;

#pragma unroll
        for (int k8 = 0; k8 < 4; k8++) {
            const int kk = k8 * 8 + lc;
            uint32_t a[4][4], b[4][2];
#pragma unroll
            for (int mi = 0; mi < 4; mi++) {
                const float* ap = sa + (wr * 64 + mi * 16 + lr) * LDSS + kk;
                a[mi][0] = __float_as_uint(ap[0]);
                a[mi][1] = __float_as_uint(ap[8 * LDSS]);
                a[mi][2] = __float_as_uint(ap[4]);
                a[mi][3] = __float_as_uint(ap[8 * LDSS + 4]);
            }
#pragma unroll
            for (int ni = 0; ni < 4; ni++) {
                const float* bp = sb + (wc * 32 + ni * 8 + lr) * LDSS + kk;
                b[ni][0] = __float_as_uint(bp[0]);
                b[ni][1] = __float_as_uint(bp[4]);
            }
#pragma unroll
            for (int mi = 0; mi < 4; mi++)
#pragma unroll
                for (int ni = 0; ni < 4; ni++)
                    asm volatile(
                        "mma.sync.aligned.m16n8k8.row.col.f32.tf32.tf32.f32 "
                        "{%0,%1,%2,%3}, {%4,%5,%6,%7}, {%8,%9}, {%0,%1,%2,%3};"
                        : "+f"(acc[mi][ni][0]), "+f"(acc[mi][ni][1]),
                          "+f"(acc[mi][ni][2]), "+f"(acc[mi][ni][3])
                        : "r"(a[mi][0]), "r"(a[mi][1]), "r"(a[mi][2]), "r"(a[mi][3]),
                          "r"(b[ni][0]), "r"(b[ni][1]));
        }
        __syncthreads();
    }

    // Epilogue: bias + optional poly-swish (+ optional tf32 re-round), float2 stores.
#pragma unroll
    for (int ni = 0; ni < 4; ni++) {
        const int col = colBase + wc * 32 + ni * 8 + 2 * lc;
        const float bv0 = __ldg(bias + col);
        const float bv1 = __ldg(bias + col + 1);
#pragma unroll
        for (int mi = 0; mi < 4; mi++) {
#pragma unroll
            for (int h = 0; h < 2; h++) {
                const int row = rowBase + wr * 64 + mi * 16 + lr + h * 8;
                float v0 = acc[mi][ni][2 * h]     + bv0;
                float v1 = acc[mi][ni][2 * h + 1] + bv1;
                if (SWISH) {
                    float s0 = fmaf(-0.0208f * v0 * v0, v0, fmaf(0.25f, v0, 0.5f));
                    float s1 = fmaf(-0.0208f * v1 * v1, v1, fmaf(0.25f, v1, 0.5f));
                    v0 *= s0; v1 *= s1;
                }
                if (ROUND_OUT) {
                    asm("cvt.rn.tf32.f32 %0, %0;" : "+f"(v0));
                    asm("cvt.rn.tf32.f32 %0, %0;" : "+f"(v1));
                }
                *reinterpret_cast<float2*>(C + (size_t)row * N + col) =
                    make_float2(v0, v1);
            }
        }
    }
}

// ------------------------- tf32 rounding pre-pass ---------------------------

__global__ void round_tf32_kernel(const float4* __restrict__ in,
                                  float4* __restrict__ out, int n4)
{
    int i = blockIdx.x * blockDim.x + threadIdx.x;
    if (i < n4) {
        float4 v = in[i];
        asm("cvt.rn.tf32.f32 %0, %0;" : "+f"(v.x));
        asm("cvt.rn.tf32.f32 %0, %0;" : "+f"(v.y));
        asm("cvt.rn.tf32.f32 %0, %0;" : "+f"(v.z));
        asm("cvt.rn.tf32.f32 %0, %0;" : "+f"(v.w));
        out[i] = v;
    }
}

// ------------------------------- launch -------------------------------------

extern "C" void kernel_launch(void* const* d_in, const int* in_sizes, int n_in,
                              void* d_out, int out_size)
{
    const float* X  = (const float*)d_in[0]; // [M, D]
    const float* W1 = (const float*)d_in[1]; // [F, D]
    const float* b1 = (const float*)d_in[2]; // [F]
    const float* W2 = (const float*)d_in[3]; // [D, F]
    const float* b2 = (const float*)d_in[4]; // [D]
    float* out = (float*)d_out;              // [M, D]

    const int F = in_sizes[2];               // 4096
    const int D = in_sizes[4];               // 1024
    const int M = in_sizes[0] / D;           // 8192

    float *mid, *Xr, *W1r, *W2r;
    cudaGetSymbolAddress((void**)&mid, g_mid);
    cudaGetSymbolAddress((void**)&Xr,  g_Xr);
    cudaGetSymbolAddress((void**)&W1r, g_W1r);
    cudaGetSymbolAddress((void**)&W2r, g_W2r);

    cudaFuncSetAttribute(ffn_gemm<true,  true >,
                         cudaFuncAttributeMaxDynamicSharedMemorySize, SMEM_DYN);
    cudaFuncSetAttribute(ffn_gemm<false, false>,
                         cudaFuncAttributeMaxDynamicSharedMemorySize, SMEM_DYN);

    // Round inputs to tf32 (RN) so MMA truncation is zero-mean.
    int n4;
    n4 = (M * D) / 4;
    round_tf32_kernel<<<(n4 + 255) / 256, 256>>>((const float4*)X,  (float4*)Xr,  n4);
    n4 = (F * D) / 4;
    round_tf32_kernel<<<(n4 + 255) / 256, 256>>>((const float4*)W1, (float4*)W1r, n4);
    n4 = (D * F) / 4;
    round_tf32_kernel<<<(n4 + 255) / 256, 256>>>((const float4*)W2, (float4*)W2r, n4);

    // GEMM1: mid = round_tf32(swish(X @ W1^T + b1))   [M, F], K = D
    {
        dim3 grid(F / BN, M / BM);
        ffn_gemm<true, true><<<grid, NTHREADS, SMEM_DYN>>>(Xr, W1r, b1, mid, M, F, D);
    }
    // GEMM2: out = mid @ W2^T + b2                    [M, D], K = F
    {
        dim3 grid(D / BN, M / BM);
        ffn_gemm<false, false><<<grid, NTHREADS, SMEM_DYN>>>(mid, W2r, b2, out, M, D, F);
    }
}